// round 13
// baseline (speedup 1.0000x reference)
#include <cuda_runtime.h>
#include <stdint.h>
#include <math.h>

#define NODES 50000
#define EDGES 600000
#define DIN 128
#define DHID 256
#define SCAN_BS 512
#define SCAN_NBLK ((NODES + SCAN_BS - 1) / SCAN_BS)   // 98

// ---------------- device scratch (static, no allocation) ----------------
__device__ int   g_cnt[NODES];
__device__ int   g_off[NODES];
__device__ int   g_cur[NODES];
__device__ int   g_csrc[EDGES];
__device__ int   g_bsum[SCAN_NBLK];
__device__ int   g_boff[SCAN_NBLK];
__device__ __align__(16) float g_z[NODES * DHID];    // x@W1r + b1l
__device__ __align__(16) float g_za[NODES * DHID];   // agg@W1l (raw)
__device__ float2 g_t12[NODES];
__device__ float2 g_w12[NODES];
__device__ float4 g_P[DHID];
__device__ float  g_c[2];
__device__ float2 g_s[NODES];

// ------- zero histogram + fold layer2/link-head into projections -------
__global__ void k_zero_prep(const float* __restrict__ W2l,
                            const float* __restrict__ W2r,
                            const float* __restrict__ Wlin,
                            const float* __restrict__ b2l)
{
    if (blockIdx.x < 196) {
        int i = blockIdx.x * 256 + threadIdx.x;
        if (i < NODES) g_cnt[i] = 0;
        return;
    }
    int j = threadIdx.x;   // 0..255 hidden index
    float u1 = 0.f, u2 = 0.f, v1 = 0.f, v2 = 0.f;
    for (int k = 0; k < DIN; k++) {
        float wa = Wlin[k], wb = Wlin[DIN + k];
        float l = W2l[j * DIN + k], r = W2r[j * DIN + k];
        u1 = fmaf(l, wa, u1); u2 = fmaf(l, wb, u2);
        v1 = fmaf(r, wa, v1); v2 = fmaf(r, wb, v2);
    }
    g_P[j] = make_float4(u1, u2, v1, v2);
    if (j == 0) {
        float c1 = 0.f, c2 = 0.f;
        for (int k = 0; k < DIN; k++) {
            c1 = fmaf(b2l[k], Wlin[k], c1);
            c2 = fmaf(b2l[k], Wlin[DIN + k], c2);
        }
        g_c[0] = c1; g_c[1] = c2;
    }
}

// ---------------- histogram of dst: 2 edges per thread ----------------
__global__ void k_hist(const int* __restrict__ dst, int E) {
    int e = (blockIdx.x * blockDim.x + threadIdx.x) * 2;
    if (e + 1 < E) {
        int2 d = *(const int2*)(dst + e);
        atomicAdd(&g_cnt[d.x], 1);
        atomicAdd(&g_cnt[d.y], 1);
    } else if (e < E) {
        atomicAdd(&g_cnt[dst[e]], 1);
    }
}

// ---------------- hierarchical scan, phase A ----------------
__global__ void __launch_bounds__(SCAN_BS) k_scanA() {
    __shared__ int s[SCAN_BS];
    int t = threadIdx.x;
    int n = blockIdx.x * SCAN_BS + t;
    int v = (n < NODES) ? g_cnt[n] : 0;
    s[t] = v;
    __syncthreads();
#pragma unroll
    for (int off = 1; off < SCAN_BS; off <<= 1) {
        int u = (t >= off) ? s[t - off] : 0;
        __syncthreads();
        s[t] += u;
        __syncthreads();
    }
    if (n < NODES) g_off[n] = s[t] - v;
    if (t == SCAN_BS - 1) g_bsum[blockIdx.x] = s[t];
}

// ---------------- phase B ----------------
__global__ void __launch_bounds__(128) k_scanB() {
    __shared__ int s[128];
    int t = threadIdx.x;
    int v = (t < SCAN_NBLK) ? g_bsum[t] : 0;
    s[t] = v;
    __syncthreads();
#pragma unroll
    for (int off = 1; off < 128; off <<= 1) {
        int u = (t >= off) ? s[t - off] : 0;
        __syncthreads();
        s[t] += u;
        __syncthreads();
    }
    if (t < SCAN_NBLK) g_boff[t] = s[t] - v;
}

// ---------------- phase C ----------------
__global__ void __launch_bounds__(SCAN_BS) k_scanC() {
    int n = blockIdx.x * SCAN_BS + threadIdx.x;
    if (n < NODES) {
        int o = g_off[n] + g_boff[blockIdx.x];
        g_off[n] = o;
        g_cur[n] = o;
    }
}

// ---------------- CSR fill: 2 edges per thread ----------------
__global__ void k_fill(const int* __restrict__ src,
                       const int* __restrict__ dst, int E) {
    int e = (blockIdx.x * blockDim.x + threadIdx.x) * 2;
    if (e + 1 < E) {
        int2 s = *(const int2*)(src + e);
        int2 d = *(const int2*)(dst + e);
        int p0 = atomicAdd(&g_cur[d.x], 1);
        g_csrc[p0] = s.x;
        int p1 = atomicAdd(&g_cur[d.y], 1);
        g_csrc[p1] = s.y;
    } else if (e < E) {
        int pos = atomicAdd(&g_cur[dst[e]], 1);
        g_csrc[pos] = src[e];
    }
}

// ======== half-GEMM X: g_z = x @ W1r + b1l  (graph-independent) ========
__global__ void __launch_bounds__(256) k_l1x(
    const float* __restrict__ x,
    const float* __restrict__ W1r, const float* __restrict__ b1l)
{
    extern __shared__ float sm[];
    float* sx = sm;             // 64 x 128 input tile
    float* sw = sm + 64 * 128;  // 32 x 256 weight K-chunk

    const int tid = threadIdx.x;
    const int node0 = blockIdx.x * 64;

    for (int i = tid; i < 64 * 32; i += 256) {
        int n = i >> 5, q = i & 31;
        int gn = node0 + n;
        float4 v = make_float4(0.f, 0.f, 0.f, 0.f);
        if (gn < NODES) v = ((const float4*)(x + (size_t)gn * DIN))[q];
        ((float4*)(sx + n * 128))[q] = v;
    }

    const int warp = tid >> 5, lane = tid & 31;
    float acc[8][8];
#pragma unroll
    for (int a = 0; a < 8; a++)
#pragma unroll
        for (int b = 0; b < 8; b++) acc[a][b] = 0.f;

    for (int kc = 0; kc < 128; kc += 32) {
        __syncthreads();
        for (int i = tid; i < 32 * 64; i += 256) {
            int kk = i >> 6, q = i & 63;
            ((float4*)(sw + kk * 256))[q] =
                ((const float4*)(W1r + (size_t)(kc + kk) * 256))[q];
        }
        __syncthreads();
#pragma unroll
        for (int kk = 0; kk < 32; kk += 4) {
            float4 xv[8];
#pragma unroll
            for (int nn = 0; nn < 8; nn++)
                xv[nn] = *((const float4*)(sx + (warp * 8 + nn) * 128 + kc + kk));
#pragma unroll
            for (int dk = 0; dk < 4; dk++) {
                float4 wa = *((const float4*)(sw + (kk + dk) * 256 + lane * 4));
                float4 wb = *((const float4*)(sw + (kk + dk) * 256 + 128 + lane * 4));
#pragma unroll
                for (int nn = 0; nn < 8; nn++) {
                    float xs = (dk == 0) ? xv[nn].x : (dk == 1) ? xv[nn].y
                             : (dk == 2) ? xv[nn].z : xv[nn].w;
                    acc[nn][0] = fmaf(xs, wa.x, acc[nn][0]);
                    acc[nn][1] = fmaf(xs, wa.y, acc[nn][1]);
                    acc[nn][2] = fmaf(xs, wa.z, acc[nn][2]);
                    acc[nn][3] = fmaf(xs, wa.w, acc[nn][3]);
                    acc[nn][4] = fmaf(xs, wb.x, acc[nn][4]);
                    acc[nn][5] = fmaf(xs, wb.y, acc[nn][5]);
                    acc[nn][6] = fmaf(xs, wb.z, acc[nn][6]);
                    acc[nn][7] = fmaf(xs, wb.w, acc[nn][7]);
                }
            }
        }
    }

    const int cA = lane * 4, cB = 128 + lane * 4;
    float4 bA = *((const float4*)(b1l + cA));
    float4 bB = *((const float4*)(b1l + cB));
#pragma unroll
    for (int nn = 0; nn < 8; nn++) {
        int gn = node0 + warp * 8 + nn;
        if (gn < NODES) {
            float4 zA = make_float4(acc[nn][0] + bA.x, acc[nn][1] + bA.y,
                                    acc[nn][2] + bA.z, acc[nn][3] + bA.w);
            float4 zB = make_float4(acc[nn][4] + bB.x, acc[nn][5] + bB.y,
                                    acc[nn][6] + bB.z, acc[nn][7] + bB.w);
            *((float4*)(g_z + (size_t)gn * DHID + cA)) = zA;
            *((float4*)(g_z + (size_t)gn * DHID + cB)) = zB;
        }
    }
}

// ======== half-GEMM A (fused aggregation, no epilogue): g_za = agg @ W1l ===
// Runs CONCURRENTLY with k_l1x (no g_z dependency).
__global__ void __launch_bounds__(256) k_l1a(
    const float* __restrict__ x, const float* __restrict__ W1l)
{
    extern __shared__ float sm[];
    float* sx = sm;             // 64 x 128 agg tile
    float* sw = sm + 64 * 128;  // 32 x 256 weight K-chunk

    const int tid = threadIdx.x;
    const int node0 = blockIdx.x * 64;
    const int warp = tid >> 5, lane = tid & 31;

    // ---- fused mean-aggregation: warp w -> nodes warp*8 .. warp*8+7 ----
#pragma unroll
    for (int nn = 0; nn < 8; nn++) {
        int gn = node0 + warp * 8 + nn;
        float4 acc = make_float4(0.f, 0.f, 0.f, 0.f);
        if (gn < NODES) {
            int start = g_off[gn], cnt = g_cnt[gn];
            int j = 0;
            for (; j + 4 <= cnt; j += 4) {
                int s0 = g_csrc[start + j];
                int s1 = g_csrc[start + j + 1];
                int s2 = g_csrc[start + j + 2];
                int s3 = g_csrc[start + j + 3];
                float4 v0 = ((const float4*)(x + (size_t)s0 * DIN))[lane];
                float4 v1 = ((const float4*)(x + (size_t)s1 * DIN))[lane];
                float4 v2 = ((const float4*)(x + (size_t)s2 * DIN))[lane];
                float4 v3 = ((const float4*)(x + (size_t)s3 * DIN))[lane];
                acc.x += (v0.x + v1.x) + (v2.x + v3.x);
                acc.y += (v0.y + v1.y) + (v2.y + v3.y);
                acc.z += (v0.z + v1.z) + (v2.z + v3.z);
                acc.w += (v0.w + v1.w) + (v2.w + v3.w);
            }
            for (; j < cnt; j++) {
                int s0 = g_csrc[start + j];
                float4 v0 = ((const float4*)(x + (size_t)s0 * DIN))[lane];
                acc.x += v0.x; acc.y += v0.y; acc.z += v0.z; acc.w += v0.w;
            }
            float r = 1.0f / fmaxf((float)cnt, 1.0f);
            acc.x *= r; acc.y *= r; acc.z *= r; acc.w *= r;
        }
        ((float4*)(sx + (warp * 8 + nn) * 128))[lane] = acc;
    }

    float acc[8][8];
#pragma unroll
    for (int a = 0; a < 8; a++)
#pragma unroll
        for (int b = 0; b < 8; b++) acc[a][b] = 0.f;

    for (int kc = 0; kc < 128; kc += 32) {
        __syncthreads();
        for (int i = tid; i < 32 * 64; i += 256) {
            int kk = i >> 6, q = i & 63;
            ((float4*)(sw + kk * 256))[q] =
                ((const float4*)(W1l + (size_t)(kc + kk) * 256))[q];
        }
        __syncthreads();
#pragma unroll
        for (int kk = 0; kk < 32; kk += 4) {
            float4 xv[8];
#pragma unroll
            for (int nn = 0; nn < 8; nn++)
                xv[nn] = *((const float4*)(sx + (warp * 8 + nn) * 128 + kc + kk));
#pragma unroll
            for (int dk = 0; dk < 4; dk++) {
                float4 wa = *((const float4*)(sw + (kk + dk) * 256 + lane * 4));
                float4 wb = *((const float4*)(sw + (kk + dk) * 256 + 128 + lane * 4));
#pragma unroll
                for (int nn = 0; nn < 8; nn++) {
                    float xs = (dk == 0) ? xv[nn].x : (dk == 1) ? xv[nn].y
                             : (dk == 2) ? xv[nn].z : xv[nn].w;
                    acc[nn][0] = fmaf(xs, wa.x, acc[nn][0]);
                    acc[nn][1] = fmaf(xs, wa.y, acc[nn][1]);
                    acc[nn][2] = fmaf(xs, wa.z, acc[nn][2]);
                    acc[nn][3] = fmaf(xs, wa.w, acc[nn][3]);
                    acc[nn][4] = fmaf(xs, wb.x, acc[nn][4]);
                    acc[nn][5] = fmaf(xs, wb.y, acc[nn][5]);
                    acc[nn][6] = fmaf(xs, wb.z, acc[nn][6]);
                    acc[nn][7] = fmaf(xs, wb.w, acc[nn][7]);
                }
            }
        }
    }

    const int cA = lane * 4, cB = 128 + lane * 4;
#pragma unroll
    for (int nn = 0; nn < 8; nn++) {
        int gn = node0 + warp * 8 + nn;
        if (gn < NODES) {
            *((float4*)(g_za + (size_t)gn * DHID + cA)) =
                make_float4(acc[nn][0], acc[nn][1], acc[nn][2], acc[nn][3]);
            *((float4*)(g_za + (size_t)gn * DHID + cB)) =
                make_float4(acc[nn][4], acc[nn][5], acc[nn][6], acc[nn][7]);
        }
    }
}

// ======== epilogue: h = relu(g_z + g_za); project onto (u1,u2,v1,v2) ======
// warp per node; lane covers cols lane*4..+3 and 128+lane*4..+3
__global__ void __launch_bounds__(256) k_epi() {
    int n = blockIdx.x * 8 + (threadIdx.x >> 5);
    if (n >= NODES) return;
    int lane = threadIdx.x & 31;
    const int cA = lane * 4, cB = 128 + lane * 4;

    float4 zA  = *((const float4*)(g_z  + (size_t)n * DHID + cA));
    float4 zB  = *((const float4*)(g_z  + (size_t)n * DHID + cB));
    float4 aA  = *((const float4*)(g_za + (size_t)n * DHID + cA));
    float4 aB  = *((const float4*)(g_za + (size_t)n * DHID + cB));

    float h0 = fmaxf(zA.x + aA.x, 0.f);
    float h1 = fmaxf(zA.y + aA.y, 0.f);
    float h2 = fmaxf(zA.z + aA.z, 0.f);
    float h3 = fmaxf(zA.w + aA.w, 0.f);
    float h4 = fmaxf(zB.x + aB.x, 0.f);
    float h5 = fmaxf(zB.y + aB.y, 0.f);
    float h6 = fmaxf(zB.z + aB.z, 0.f);
    float h7 = fmaxf(zB.w + aB.w, 0.f);

    float4 P0 = g_P[cA], P1 = g_P[cA + 1], P2 = g_P[cA + 2], P3 = g_P[cA + 3];
    float4 Q0 = g_P[cB], Q1 = g_P[cB + 1], Q2 = g_P[cB + 2], Q3 = g_P[cB + 3];

    float t1 = h0*P0.x + h1*P1.x + h2*P2.x + h3*P3.x
             + h4*Q0.x + h5*Q1.x + h6*Q2.x + h7*Q3.x;
    float t2 = h0*P0.y + h1*P1.y + h2*P2.y + h3*P3.y
             + h4*Q0.y + h5*Q1.y + h6*Q2.y + h7*Q3.y;
    float w1 = h0*P0.z + h1*P1.z + h2*P2.z + h3*P3.z
             + h4*Q0.z + h5*Q1.z + h6*Q2.z + h7*Q3.z;
    float w2 = h0*P0.w + h1*P1.w + h2*P2.w + h3*P3.w
             + h4*Q0.w + h5*Q1.w + h6*Q2.w + h7*Q3.w;
#pragma unroll
    for (int off = 16; off > 0; off >>= 1) {
        t1 += __shfl_xor_sync(0xffffffffu, t1, off);
        t2 += __shfl_xor_sync(0xffffffffu, t2, off);
        w1 += __shfl_xor_sync(0xffffffffu, w1, off);
        w2 += __shfl_xor_sync(0xffffffffu, w2, off);
    }
    if (lane == 0) {
        g_t12[n] = make_float2(t1, t2);
        g_w12[n] = make_float2(w1, w2);
    }
}

// -------- layer-2 aggregate (gather) + finalize, 4 lanes per node ------
__global__ void k_fin() {
    int g = blockIdx.x * blockDim.x + threadIdx.x;
    int n = g >> 2, l = g & 3;
    if (n >= NODES) return;
    int start = g_off[n], cnt = g_cnt[n];
    float a1 = 0.f, a2 = 0.f;
    for (int j = l; j < cnt; j += 4) {
        float2 t = g_t12[g_csrc[start + j]];
        a1 += t.x; a2 += t.y;
    }
#pragma unroll
    for (int off = 1; off <= 2; off <<= 1) {
        a1 += __shfl_xor_sync(0xffffffffu, a1, off);
        a2 += __shfl_xor_sync(0xffffffffu, a2, off);
    }
    if (l == 0) {
        float r = 1.0f / fmaxf((float)cnt, 1.0f);
        float2 w = g_w12[n];
        g_s[n] = make_float2(a1 * r + w.x + g_c[0],
                             a2 * r + w.y + g_c[1]);
    }
}

// -------- pair head: sigmoid(s1[i] + s2[j] + blin) --------
__global__ void k_pairs(const int* __restrict__ mask,
                        const float* __restrict__ blin,
                        float* __restrict__ out, int P)
{
    int p = blockIdx.x * blockDim.x + threadIdx.x;
    if (p >= P) return;
    int2 m = ((const int2*)mask)[p];
    float z = g_s[m.x].x + g_s[m.y].y + blin[0];
    out[p] = 1.0f / (1.0f + expf(-z));
}

// ---------------- launch ----------------
extern "C" void kernel_launch(void* const* d_in, const int* in_sizes, int n_in,
                              void* d_out, int out_size)
{
    const float* x    = (const float*)d_in[0];
    const int*   ei   = (const int*)d_in[1];
    const int*   mask = (const int*)d_in[2];
    const float* W1l  = (const float*)d_in[3];
    const float* b1l  = (const float*)d_in[4];
    const float* W1r  = (const float*)d_in[5];
    const float* W2l  = (const float*)d_in[6];
    const float* b2l  = (const float*)d_in[7];
    const float* W2r  = (const float*)d_in[8];
    const float* Wlin = (const float*)d_in[9];
    const float* blin = (const float*)d_in[10];
    float* out = (float*)d_out;

    int E = in_sizes[1] / 2;
    int P = in_sizes[2] / 2;
    const int* src = ei;
    const int* dst = ei + E;

    // one-time host resources (created on the first, non-captured call)
    static cudaStream_t s2 = nullptr;
    static cudaEvent_t evF = nullptr, evJ = nullptr;
    if (s2 == nullptr) {
        cudaStreamCreateWithFlags(&s2, cudaStreamNonBlocking);
        cudaEventCreateWithFlags(&evF, cudaEventDisableTiming);
        cudaEventCreateWithFlags(&evJ, cudaEventDisableTiming);
        const int SM = (64 * 128 + 32 * 256) * sizeof(float);  // 64 KB
        cudaFuncSetAttribute((const void*)k_l1x,
                             cudaFuncAttributeMaxDynamicSharedMemorySize, SM);
        cudaFuncSetAttribute((const void*)k_l1a,
                             cudaFuncAttributeMaxDynamicSharedMemorySize, SM);
    }
    const int SMEM = (64 * 128 + 32 * 256) * sizeof(float);    // 64 KB
    const int GRID = (NODES + 63) / 64;

    // fork: x@W1r half-GEMM on stream 2, fully independent
    cudaEventRecord(evF, 0);
    cudaStreamWaitEvent(s2, evF, 0);
    k_l1x<<<GRID, 256, SMEM, s2>>>(x, W1r, b1l);
    cudaEventRecord(evJ, s2);

    // stream 1: CSR chain, then agg half-GEMM (no g_z dependency —
    // runs concurrently with k_l1x)
    k_zero_prep<<<197, 256>>>(W2l, W2r, Wlin, b2l);
    k_hist<<<(E / 2 + 255) / 256, 256>>>(dst, E);
    k_scanA<<<SCAN_NBLK, SCAN_BS>>>();
    k_scanB<<<1, 128>>>();
    k_scanC<<<SCAN_NBLK, SCAN_BS>>>();
    k_fill<<<(E / 2 + 255) / 256, 256>>>(src, dst, E);
    k_l1a<<<GRID, 256, SMEM>>>(x, W1l);

    // join both GEMMs, then epilogue + layer-2 + pair head
    cudaStreamWaitEvent(0, evJ, 0);
    k_epi<<<(NODES + 7) / 8, 256>>>();
    k_fin<<<(NODES * 4 + 255) / 256, 256>>>();
    k_pairs<<<(P + 255) / 256, 256>>>(mask, blin, out, P);
}

// round 14
// speedup vs baseline: 1.1305x; 1.1305x over previous
#include <cuda_runtime.h>
#include <stdint.h>
#include <math.h>

#define NODES 50000
#define EDGES 600000
#define DIN 128
#define DHID 256
#define SCAN_BS 512
#define SCAN_NBLK ((NODES + SCAN_BS - 1) / SCAN_BS)   // 98

// ---------------- device scratch (static, no allocation) ----------------
__device__ int   g_cnt[NODES];
__device__ int   g_off[NODES];
__device__ int   g_cur[NODES];
__device__ int   g_csrc[EDGES];
__device__ int   g_bsum[SCAN_NBLK];
__device__ int   g_boff[SCAN_NBLK];
__device__ __align__(16) float g_y[NODES * DHID];    // x @ W1l
__device__ __align__(16) float g_z[NODES * DHID];    // x @ W1r
__device__ __align__(16) float g_za[NODES * DHID];   // mean-gather of y
__device__ float2 g_t12[NODES];
__device__ float2 g_w12[NODES];
__device__ float4 g_P[DHID];
__device__ float  g_c[2];
__device__ float2 g_s[NODES];

// ------- zero histogram + fold layer2/link-head into projections -------
__global__ void k_zero_prep(const float* __restrict__ W2l,
                            const float* __restrict__ W2r,
                            const float* __restrict__ Wlin,
                            const float* __restrict__ b2l)
{
    if (blockIdx.x < 196) {
        int i = blockIdx.x * 256 + threadIdx.x;
        if (i < NODES) g_cnt[i] = 0;
        return;
    }
    int j = threadIdx.x;   // 0..255 hidden index
    float u1 = 0.f, u2 = 0.f, v1 = 0.f, v2 = 0.f;
    for (int k = 0; k < DIN; k++) {
        float wa = Wlin[k], wb = Wlin[DIN + k];
        float l = W2l[j * DIN + k], r = W2r[j * DIN + k];
        u1 = fmaf(l, wa, u1); u2 = fmaf(l, wb, u2);
        v1 = fmaf(r, wa, v1); v2 = fmaf(r, wb, v2);
    }
    g_P[j] = make_float4(u1, u2, v1, v2);
    if (j == 0) {
        float c1 = 0.f, c2 = 0.f;
        for (int k = 0; k < DIN; k++) {
            c1 = fmaf(b2l[k], Wlin[k], c1);
            c2 = fmaf(b2l[k], Wlin[DIN + k], c2);
        }
        g_c[0] = c1; g_c[1] = c2;
    }
}

// ---------------- histogram of dst: 2 edges per thread ----------------
__global__ void k_hist(const int* __restrict__ dst, int E) {
    int e = (blockIdx.x * blockDim.x + threadIdx.x) * 2;
    if (e + 1 < E) {
        int2 d = *(const int2*)(dst + e);
        atomicAdd(&g_cnt[d.x], 1);
        atomicAdd(&g_cnt[d.y], 1);
    } else if (e < E) {
        atomicAdd(&g_cnt[dst[e]], 1);
    }
}

// ---------------- hierarchical scan ----------------
__global__ void __launch_bounds__(SCAN_BS) k_scanA() {
    __shared__ int s[SCAN_BS];
    int t = threadIdx.x;
    int n = blockIdx.x * SCAN_BS + t;
    int v = (n < NODES) ? g_cnt[n] : 0;
    s[t] = v;
    __syncthreads();
#pragma unroll
    for (int off = 1; off < SCAN_BS; off <<= 1) {
        int u = (t >= off) ? s[t - off] : 0;
        __syncthreads();
        s[t] += u;
        __syncthreads();
    }
    if (n < NODES) g_off[n] = s[t] - v;
    if (t == SCAN_BS - 1) g_bsum[blockIdx.x] = s[t];
}

__global__ void __launch_bounds__(128) k_scanB() {
    __shared__ int s[128];
    int t = threadIdx.x;
    int v = (t < SCAN_NBLK) ? g_bsum[t] : 0;
    s[t] = v;
    __syncthreads();
#pragma unroll
    for (int off = 1; off < 128; off <<= 1) {
        int u = (t >= off) ? s[t - off] : 0;
        __syncthreads();
        s[t] += u;
        __syncthreads();
    }
    if (t < SCAN_NBLK) g_boff[t] = s[t] - v;
}

__global__ void __launch_bounds__(SCAN_BS) k_scanC() {
    int n = blockIdx.x * SCAN_BS + threadIdx.x;
    if (n < NODES) {
        int o = g_off[n] + g_boff[blockIdx.x];
        g_off[n] = o;
        g_cur[n] = o;
    }
}

// ---------------- CSR fill: 2 edges per thread ----------------
__global__ void k_fill(const int* __restrict__ src,
                       const int* __restrict__ dst, int E) {
    int e = (blockIdx.x * blockDim.x + threadIdx.x) * 2;
    if (e + 1 < E) {
        int2 s = *(const int2*)(src + e);
        int2 d = *(const int2*)(dst + e);
        int p0 = atomicAdd(&g_cur[d.x], 1);
        g_csrc[p0] = s.x;
        int p1 = atomicAdd(&g_cur[d.y], 1);
        g_csrc[p1] = s.y;
    } else if (e < E) {
        int pos = atomicAdd(&g_cur[dst[e]], 1);
        g_csrc[pos] = src[e];
    }
}

// ======== GEMM: out = x @ W  (50000 x 256 x 128), no bias ========
__global__ void __launch_bounds__(256) k_gemm(
    const float* __restrict__ x,
    const float* __restrict__ W, float* __restrict__ out)
{
    extern __shared__ float sm[];
    float* sx = sm;             // 64 x 128 input tile
    float* sw = sm + 64 * 128;  // 32 x 256 weight K-chunk

    const int tid = threadIdx.x;
    const int node0 = blockIdx.x * 64;

    for (int i = tid; i < 64 * 32; i += 256) {
        int n = i >> 5, q = i & 31;
        int gn = node0 + n;
        float4 v = make_float4(0.f, 0.f, 0.f, 0.f);
        if (gn < NODES) v = ((const float4*)(x + (size_t)gn * DIN))[q];
        ((float4*)(sx + n * 128))[q] = v;
    }

    const int warp = tid >> 5, lane = tid & 31;
    float acc[8][8];
#pragma unroll
    for (int a = 0; a < 8; a++)
#pragma unroll
        for (int b = 0; b < 8; b++) acc[a][b] = 0.f;

    for (int kc = 0; kc < 128; kc += 32) {
        __syncthreads();
        for (int i = tid; i < 32 * 64; i += 256) {
            int kk = i >> 6, q = i & 63;
            ((float4*)(sw + kk * 256))[q] =
                ((const float4*)(W + (size_t)(kc + kk) * 256))[q];
        }
        __syncthreads();
#pragma unroll
        for (int kk = 0; kk < 32; kk += 4) {
            float4 xv[8];
#pragma unroll
            for (int nn = 0; nn < 8; nn++)
                xv[nn] = *((const float4*)(sx + (warp * 8 + nn) * 128 + kc + kk));
#pragma unroll
            for (int dk = 0; dk < 4; dk++) {
                float4 wa = *((const float4*)(sw + (kk + dk) * 256 + lane * 4));
                float4 wb = *((const float4*)(sw + (kk + dk) * 256 + 128 + lane * 4));
#pragma unroll
                for (int nn = 0; nn < 8; nn++) {
                    float xs = (dk == 0) ? xv[nn].x : (dk == 1) ? xv[nn].y
                             : (dk == 2) ? xv[nn].z : xv[nn].w;
                    acc[nn][0] = fmaf(xs, wa.x, acc[nn][0]);
                    acc[nn][1] = fmaf(xs, wa.y, acc[nn][1]);
                    acc[nn][2] = fmaf(xs, wa.z, acc[nn][2]);
                    acc[nn][3] = fmaf(xs, wa.w, acc[nn][3]);
                    acc[nn][4] = fmaf(xs, wb.x, acc[nn][4]);
                    acc[nn][5] = fmaf(xs, wb.y, acc[nn][5]);
                    acc[nn][6] = fmaf(xs, wb.z, acc[nn][6]);
                    acc[nn][7] = fmaf(xs, wb.w, acc[nn][7]);
                }
            }
        }
    }

    const int cA = lane * 4, cB = 128 + lane * 4;
#pragma unroll
    for (int nn = 0; nn < 8; nn++) {
        int gn = node0 + warp * 8 + nn;
        if (gn < NODES) {
            *((float4*)(out + (size_t)gn * DHID + cA)) =
                make_float4(acc[nn][0], acc[nn][1], acc[nn][2], acc[nn][3]);
            *((float4*)(out + (size_t)gn * DHID + cB)) =
                make_float4(acc[nn][4], acc[nn][5], acc[nn][6], acc[nn][7]);
        }
    }
}

// ======== gather in output space: g_za[n] = mean over nbrs of g_y ========
// warp per node; lane covers cols lane*4..+3 and 128+lane*4..+3
__global__ void __launch_bounds__(256) k_gath() {
    int n = blockIdx.x * 8 + (threadIdx.x >> 5);
    if (n >= NODES) return;
    int lane = threadIdx.x & 31;
    const int cA = lane * 4, cB = 128 + lane * 4;
    int start = g_off[n], cnt = g_cnt[n];

    float4 aA = make_float4(0.f, 0.f, 0.f, 0.f);
    float4 aB = make_float4(0.f, 0.f, 0.f, 0.f);
    int j = 0;
    for (; j + 2 <= cnt; j += 2) {
        int s0 = g_csrc[start + j];
        int s1 = g_csrc[start + j + 1];
        const float* r0 = g_y + (size_t)s0 * DHID;
        const float* r1 = g_y + (size_t)s1 * DHID;
        float4 vA0 = *((const float4*)(r0 + cA));
        float4 vB0 = *((const float4*)(r0 + cB));
        float4 vA1 = *((const float4*)(r1 + cA));
        float4 vB1 = *((const float4*)(r1 + cB));
        aA.x += vA0.x + vA1.x; aA.y += vA0.y + vA1.y;
        aA.z += vA0.z + vA1.z; aA.w += vA0.w + vA1.w;
        aB.x += vB0.x + vB1.x; aB.y += vB0.y + vB1.y;
        aB.z += vB0.z + vB1.z; aB.w += vB0.w + vB1.w;
    }
    if (j < cnt) {
        int s0 = g_csrc[start + j];
        const float* r0 = g_y + (size_t)s0 * DHID;
        float4 vA0 = *((const float4*)(r0 + cA));
        float4 vB0 = *((const float4*)(r0 + cB));
        aA.x += vA0.x; aA.y += vA0.y; aA.z += vA0.z; aA.w += vA0.w;
        aB.x += vB0.x; aB.y += vB0.y; aB.z += vB0.z; aB.w += vB0.w;
    }
    float r = 1.0f / fmaxf((float)cnt, 1.0f);
    aA.x *= r; aA.y *= r; aA.z *= r; aA.w *= r;
    aB.x *= r; aB.y *= r; aB.z *= r; aB.w *= r;
    *((float4*)(g_za + (size_t)n * DHID + cA)) = aA;
    *((float4*)(g_za + (size_t)n * DHID + cB)) = aB;
}

// ======== epilogue: h = relu(g_z + g_za + b1l); project ========
__global__ void __launch_bounds__(256) k_epi(const float* __restrict__ b1l) {
    int n = blockIdx.x * 8 + (threadIdx.x >> 5);
    if (n >= NODES) return;
    int lane = threadIdx.x & 31;
    const int cA = lane * 4, cB = 128 + lane * 4;

    float4 zA = *((const float4*)(g_z  + (size_t)n * DHID + cA));
    float4 zB = *((const float4*)(g_z  + (size_t)n * DHID + cB));
    float4 aA = *((const float4*)(g_za + (size_t)n * DHID + cA));
    float4 aB = *((const float4*)(g_za + (size_t)n * DHID + cB));
    float4 bA = *((const float4*)(b1l + cA));
    float4 bB = *((const float4*)(b1l + cB));

    float h0 = fmaxf(zA.x + aA.x + bA.x, 0.f);
    float h1 = fmaxf(zA.y + aA.y + bA.y, 0.f);
    float h2 = fmaxf(zA.z + aA.z + bA.z, 0.f);
    float h3 = fmaxf(zA.w + aA.w + bA.w, 0.f);
    float h4 = fmaxf(zB.x + aB.x + bB.x, 0.f);
    float h5 = fmaxf(zB.y + aB.y + bB.y, 0.f);
    float h6 = fmaxf(zB.z + aB.z + bB.z, 0.f);
    float h7 = fmaxf(zB.w + aB.w + bB.w, 0.f);

    float4 P0 = g_P[cA], P1 = g_P[cA + 1], P2 = g_P[cA + 2], P3 = g_P[cA + 3];
    float4 Q0 = g_P[cB], Q1 = g_P[cB + 1], Q2 = g_P[cB + 2], Q3 = g_P[cB + 3];

    float t1 = h0*P0.x + h1*P1.x + h2*P2.x + h3*P3.x
             + h4*Q0.x + h5*Q1.x + h6*Q2.x + h7*Q3.x;
    float t2 = h0*P0.y + h1*P1.y + h2*P2.y + h3*P3.y
             + h4*Q0.y + h5*Q1.y + h6*Q2.y + h7*Q3.y;
    float w1 = h0*P0.z + h1*P1.z + h2*P2.z + h3*P3.z
             + h4*Q0.z + h5*Q1.z + h6*Q2.z + h7*Q3.z;
    float w2 = h0*P0.w + h1*P1.w + h2*P2.w + h3*P3.w
             + h4*Q0.w + h5*Q1.w + h6*Q2.w + h7*Q3.w;
#pragma unroll
    for (int off = 16; off > 0; off >>= 1) {
        t1 += __shfl_xor_sync(0xffffffffu, t1, off);
        t2 += __shfl_xor_sync(0xffffffffu, t2, off);
        w1 += __shfl_xor_sync(0xffffffffu, w1, off);
        w2 += __shfl_xor_sync(0xffffffffu, w2, off);
    }
    if (lane == 0) {
        g_t12[n] = make_float2(t1, t2);
        g_w12[n] = make_float2(w1, w2);
    }
}

// -------- layer-2 aggregate (gather) + finalize, 4 lanes per node ------
__global__ void k_fin() {
    int g = blockIdx.x * blockDim.x + threadIdx.x;
    int n = g >> 2, l = g & 3;
    if (n >= NODES) return;
    int start = g_off[n], cnt = g_cnt[n];
    float a1 = 0.f, a2 = 0.f;
    for (int j = l; j < cnt; j += 4) {
        float2 t = g_t12[g_csrc[start + j]];
        a1 += t.x; a2 += t.y;
    }
#pragma unroll
    for (int off = 1; off <= 2; off <<= 1) {
        a1 += __shfl_xor_sync(0xffffffffu, a1, off);
        a2 += __shfl_xor_sync(0xffffffffu, a2, off);
    }
    if (l == 0) {
        float r = 1.0f / fmaxf((float)cnt, 1.0f);
        float2 w = g_w12[n];
        g_s[n] = make_float2(a1 * r + w.x + g_c[0],
                             a2 * r + w.y + g_c[1]);
    }
}

// -------- pair head: sigmoid(s1[i] + s2[j] + blin) --------
__global__ void k_pairs(const int* __restrict__ mask,
                        const float* __restrict__ blin,
                        float* __restrict__ out, int P)
{
    int p = blockIdx.x * blockDim.x + threadIdx.x;
    if (p >= P) return;
    int2 m = ((const int2*)mask)[p];
    float z = g_s[m.x].x + g_s[m.y].y + blin[0];
    out[p] = 1.0f / (1.0f + expf(-z));
}

// ---------------- launch ----------------
extern "C" void kernel_launch(void* const* d_in, const int* in_sizes, int n_in,
                              void* d_out, int out_size)
{
    const float* x    = (const float*)d_in[0];
    const int*   ei   = (const int*)d_in[1];
    const int*   mask = (const int*)d_in[2];
    const float* W1l  = (const float*)d_in[3];
    const float* b1l  = (const float*)d_in[4];
    const float* W1r  = (const float*)d_in[5];
    const float* W2l  = (const float*)d_in[6];
    const float* b2l  = (const float*)d_in[7];
    const float* W2r  = (const float*)d_in[8];
    const float* Wlin = (const float*)d_in[9];
    const float* blin = (const float*)d_in[10];
    float* out = (float*)d_out;

    int E = in_sizes[1] / 2;
    int P = in_sizes[2] / 2;
    const int* src = ei;
    const int* dst = ei + E;

    // one-time host resources (created on the first, non-captured call)
    static cudaStream_t s2 = nullptr;
    static cudaEvent_t evY = nullptr, evG = nullptr;
    static float *py = nullptr, *pz = nullptr;
    if (s2 == nullptr) {
        cudaStreamCreateWithFlags(&s2, cudaStreamNonBlocking);
        cudaEventCreateWithFlags(&evY, cudaEventDisableTiming);
        cudaEventCreateWithFlags(&evG, cudaEventDisableTiming);
        cudaGetSymbolAddress((void**)&py, g_y);
        cudaGetSymbolAddress((void**)&pz, g_z);
        const int SM = (64 * 128 + 32 * 256) * sizeof(float);  // 64 KB
        cudaFuncSetAttribute((const void*)k_gemm,
                             cudaFuncAttributeMaxDynamicSharedMemorySize, SM);
    }
    const int SMEM = (64 * 128 + 32 * 256) * sizeof(float);    // 64 KB
    const int GRID = (NODES + 63) / 64;

    // stream 1 (default): the two FFMA GEMMs back-to-back, no dependencies
    k_gemm<<<GRID, 256, SMEM>>>(x, W1l, py);   // y = x @ W1l
    cudaEventRecord(evY, 0);
    k_gemm<<<GRID, 256, SMEM>>>(x, W1r, pz);   // z = x @ W1r

    // stream 2: CSR chain, then output-space gather (overlaps the z GEMM)
    k_zero_prep<<<197, 256, 0, s2>>>(W2l, W2r, Wlin, b2l);
    k_hist<<<(E / 2 + 255) / 256, 256, 0, s2>>>(dst, E);
    k_scanA<<<SCAN_NBLK, SCAN_BS, 0, s2>>>();
    k_scanB<<<1, 128, 0, s2>>>();
    k_scanC<<<SCAN_NBLK, SCAN_BS, 0, s2>>>();
    k_fill<<<(E / 2 + 255) / 256, 256, 0, s2>>>(src, dst, E);
    cudaStreamWaitEvent(s2, evY, 0);
    k_gath<<<(NODES + 7) / 8, 256, 0, s2>>>();
    cudaEventRecord(evG, s2);

    // join: epilogue + layer-2 + pair head
    cudaStreamWaitEvent(0, evG, 0);
    k_epi<<<(NODES + 7) / 8, 256>>>(b1l);
    k_fin<<<(NODES * 4 + 255) / 256, 256>>>();
    k_pairs<<<(P + 255) / 256, 256>>>(mask, blin, out, P);
}